// round 12
// baseline (speedup 1.0000x reference)
#include <cuda_runtime.h>
#include <cuda_bf16.h>
#include <cstdint>

#define Bb   64
#define Tt   256
#define Ii   512
#define Oo   512
#define NOBS 128
#define ETA  0.01f
#define CH   32
#define NCH  (Tt / CH)

typedef unsigned long long u64;

// ---- scratch (static __device__, no allocs) ----
__device__ __align__(16) float G_buf[Bb * Tt * Tt];
__device__ __align__(16) float D_buf[Bb * Tt * Oo];
__device__ __align__(16) float U_buf[Bb * Tt * Oo];
__device__ __align__(16) __nv_bfloat16 Xhi_g[Bb * Tt * Ii];
__device__ __align__(16) __nv_bfloat16 Xlo_g[Bb * Tt * Ii];
__device__ __align__(16) __nv_bfloat16 Whi_g[Bb * Oo * Ii];
__device__ __align__(16) __nv_bfloat16 Wlo_g[Bb * Oo * Ii];

// ---- packed f32x2 helpers ----
__device__ __forceinline__ u64 pack2(float x, float y) {
    u64 r; asm("mov.b64 %0, {%1, %2};" : "=l"(r) : "f"(x), "f"(y)); return r;
}
__device__ __forceinline__ void unpack2(u64 v, float& x, float& y) {
    asm("mov.b64 {%0, %1}, %2;" : "=f"(x), "=f"(y) : "l"(v));
}
__device__ __forceinline__ u64 ffma2(u64 a, u64 b, u64 c) {
    u64 d; asm("fma.rn.f32x2 %0, %1, %2, %3;" : "=l"(d) : "l"(a), "l"(b), "l"(c)); return d;
}

// ---- mma.sync / cp.async helpers ----
__device__ __forceinline__ uint32_t smem_u32(const void* p) {
    uint32_t a;
    asm("{ .reg .u64 t; cvta.to.shared.u64 t, %1; cvt.u32.u64 %0, t; }" : "=r"(a) : "l"(p));
    return a;
}
__device__ __forceinline__ void ldsm4(uint32_t addr, uint32_t r[4]) {
    asm volatile("ldmatrix.sync.aligned.m8n8.x4.shared.b16 {%0,%1,%2,%3}, [%4];"
                 : "=r"(r[0]), "=r"(r[1]), "=r"(r[2]), "=r"(r[3]) : "r"(addr));
}
__device__ __forceinline__ void mma16816(float c[4], const uint32_t a[4],
                                         uint32_t b0, uint32_t b1) {
    asm volatile("mma.sync.aligned.m16n8k16.row.col.f32.bf16.bf16.f32 "
                 "{%0,%1,%2,%3}, {%4,%5,%6,%7}, {%8,%9}, {%0,%1,%2,%3};"
                 : "+f"(c[0]), "+f"(c[1]), "+f"(c[2]), "+f"(c[3])
                 : "r"(a[0]), "r"(a[1]), "r"(a[2]), "r"(a[3]), "r"(b0), "r"(b1));
}
#define CP_ASYNC16(dst, src) asm volatile("cp.async.cg.shared.global [%0], [%1], 16;" :: "r"(dst), "l"(src))
#define CP_COMMIT()          asm volatile("cp.async.commit_group;" ::: "memory")
#define CP_WAIT(n)           asm volatile("cp.async.wait_group %0;" :: "n"(n) : "memory")

#define SWZ(x) ((x) ^ (((x) >> 3) & 0x70))

// ============================================================
// bf16 hi/lo split conversion
// ============================================================
__device__ __forceinline__ void split_store(const float* __restrict__ src,
                                            __nv_bfloat16* __restrict__ hi,
                                            __nv_bfloat16* __restrict__ lo, int i)
{
    float4 v = reinterpret_cast<const float4*>(src)[i];
    __nv_bfloat16 h0 = __float2bfloat16(v.x), h1 = __float2bfloat16(v.y);
    __nv_bfloat16 h2 = __float2bfloat16(v.z), h3 = __float2bfloat16(v.w);
    __nv_bfloat16 l0 = __float2bfloat16(v.x - __bfloat162float(h0));
    __nv_bfloat16 l1 = __float2bfloat16(v.y - __bfloat162float(h1));
    __nv_bfloat16 l2 = __float2bfloat16(v.z - __bfloat162float(h2));
    __nv_bfloat16 l3 = __float2bfloat16(v.w - __bfloat162float(h3));
    reinterpret_cast<__nv_bfloat162*>(hi)[2 * i]     = __nv_bfloat162(h0, h1);
    reinterpret_cast<__nv_bfloat162*>(hi)[2 * i + 1] = __nv_bfloat162(h2, h3);
    reinterpret_cast<__nv_bfloat162*>(lo)[2 * i]     = __nv_bfloat162(l0, l1);
    reinterpret_cast<__nv_bfloat162*>(lo)[2 * i + 1] = __nv_bfloat162(l2, l3);
}

__global__ void __launch_bounds__(256)
split_x(const float* __restrict__ X)
{
    int i = blockIdx.x * 256 + threadIdx.x;
    if (i < Bb * Tt * Ii / 4) split_store(X, Xhi_g, Xlo_g, i);
}

__global__ void __launch_bounds__(256)
split_w(const float* __restrict__ W)
{
    int i = blockIdx.x * 256 + threadIdx.x;
    if (i < Bb * Oo * Ii / 4) split_store(W, Whi_g, Wlo_g, i);
}

// ============================================================
// mma.sync bf16 3-term-split GEMM (byte-identical to the 307 us run)
// ============================================================
#define KC       64
#define NKC      (Ii / KC)
#define SM_TILE  16384
#define SM_STAGE (4 * SM_TILE)
#define SM_TOTAL (2 * SM_STAGE)

template<int M, int N, bool TRI>
__device__ __forceinline__ void gemm_core(const __nv_bfloat16* __restrict__ AH,
                                          const __nv_bfloat16* __restrict__ AL,
                                          const __nv_bfloat16* __restrict__ BH,
                                          const __nv_bfloat16* __restrict__ BL,
                                          float* __restrict__ Cg)
{
    const int nx = blockIdx.x, my = blockIdx.y, b = blockIdx.z;
    if (TRI && my > nx) return;

    extern __shared__ __align__(1024) char smem[];
    const uint32_t sb = smem_u32(smem);
    const int tid = threadIdx.x;
    const int wid = tid >> 5;
    const int l   = tid & 31;

    const int warp_m = wid & 1;
    const int warp_n = wid >> 1;

    const __nv_bfloat16* gbase[4];
    gbase[0] = AH + ((size_t)b * M + my * 128) * Ii;
    gbase[1] = AL + ((size_t)b * M + my * 128) * Ii;
    gbase[2] = BH + ((size_t)b * N + nx * 128) * Ii;
    gbase[3] = BL + ((size_t)b * N + nx * 128) * Ii;

    int  s_arr[16], s_rw[16], s_un[16];
    uint32_t s_dst[16];
    #pragma unroll
    for (int i = 0; i < 16; i++) {
        const int u = tid + 256 * i;
        s_arr[i] = u >> 10;
        const int rem = u & 1023;
        s_rw[i] = rem >> 3;
        s_un[i] = rem & 7;
        s_dst[i] = (uint32_t)(s_arr[i] * SM_TILE + SWZ(s_rw[i] * 128 + s_un[i] * 16));
    }

    const int g = l >> 3, r = l & 7;
    const uint32_t aoff = (uint32_t)(warp_m * 64 + (g & 1) * 8 + r) * 128;
    const uint32_t akb  = (uint32_t)((g >> 1) * 16);
    const uint32_t boff = (uint32_t)(warp_n * 32 + (g >> 1) * 8 + r) * 128;
    const uint32_t bkb  = (uint32_t)((g & 1) * 16);
    const uint32_t lxor = (uint32_t)(r << 4);

    float c[4][4][4];
    #pragma unroll
    for (int mt = 0; mt < 4; mt++)
        #pragma unroll
        for (int nt = 0; nt < 4; nt++)
            #pragma unroll
            for (int q = 0; q < 4; q++) c[mt][nt][q] = 0.0f;

    #pragma unroll
    for (int i = 0; i < 16; i++) {
        const __nv_bfloat16* src = gbase[s_arr[i]] + (size_t)s_rw[i] * Ii + s_un[i] * 8;
        CP_ASYNC16(sb + s_dst[i], src);
    }
    CP_COMMIT();

    for (int ck = 0; ck < NKC; ck++) {
        const uint32_t buf = sb + (uint32_t)((ck & 1) * SM_STAGE);

        if (ck + 1 < NKC) {
            const uint32_t nbuf = (uint32_t)(((ck + 1) & 1) * SM_STAGE);
            const int koff = (ck + 1) * KC;
            #pragma unroll
            for (int i = 0; i < 16; i++) {
                const __nv_bfloat16* src =
                    gbase[s_arr[i]] + (size_t)s_rw[i] * Ii + koff + s_un[i] * 8;
                CP_ASYNC16(sb + nbuf + s_dst[i], src);
            }
            CP_COMMIT();
            CP_WAIT(1);
        } else {
            CP_WAIT(0);
        }
        __syncthreads();

        const uint32_t As_hi = buf;
        const uint32_t As_lo = buf + SM_TILE;
        const uint32_t Bs_hi = buf + 2 * SM_TILE;
        const uint32_t Bs_lo = buf + 3 * SM_TILE;

        #pragma unroll
        for (int ks = 0; ks < 4; ks++) {
            const uint32_t kb = (uint32_t)(ks * 32);

            uint32_t bh[4][2], bl[4][2];
            #pragma unroll
            for (int nt2 = 0; nt2 < 2; nt2++) {
                uint32_t t4[4];
                const uint32_t badd = boff + nt2 * 2048 + ((kb + bkb) ^ lxor);
                ldsm4(Bs_hi + badd, t4);
                bh[2 * nt2][0] = t4[0]; bh[2 * nt2][1] = t4[1];
                bh[2 * nt2 + 1][0] = t4[2]; bh[2 * nt2 + 1][1] = t4[3];
                ldsm4(Bs_lo + badd, t4);
                bl[2 * nt2][0] = t4[0]; bl[2 * nt2][1] = t4[1];
                bl[2 * nt2 + 1][0] = t4[2]; bl[2 * nt2 + 1][1] = t4[3];
            }

            #pragma unroll
            for (int mt = 0; mt < 4; mt++) {
                const uint32_t aadd = aoff + mt * 2048 + ((kb + akb) ^ lxor);
                uint32_t a4[4];
                ldsm4(As_hi + aadd, a4);
                #pragma unroll
                for (int nt = 0; nt < 4; nt++) {
                    mma16816(c[mt][nt], a4, bh[nt][0], bh[nt][1]);
                    mma16816(c[mt][nt], a4, bl[nt][0], bl[nt][1]);
                }
                ldsm4(As_lo + aadd, a4);
                #pragma unroll
                for (int nt = 0; nt < 4; nt++)
                    mma16816(c[mt][nt], a4, bh[nt][0], bh[nt][1]);
            }
        }
        __syncthreads();
    }

    float* Crow = Cg + ((size_t)b * M + my * 128) * N + nx * 128;
    const int qr = l >> 2, qc = l & 3;
    #pragma unroll
    for (int mt = 0; mt < 4; mt++) {
        const int m0 = warp_m * 64 + mt * 16;
        #pragma unroll
        for (int nt = 0; nt < 4; nt++) {
            const int n0 = warp_n * 32 + nt * 8 + 2 * qc;
            *reinterpret_cast<float2*>(&Crow[(size_t)(m0 + qr) * N + n0]) =
                make_float2(c[mt][nt][0], c[mt][nt][1]);
            *reinterpret_cast<float2*>(&Crow[(size_t)(m0 + qr + 8) * N + n0]) =
                make_float2(c[mt][nt][2], c[mt][nt][3]);
        }
    }
}

__global__ void __launch_bounds__(256, 1)
gemm_g_k() { gemm_core<Tt, Tt, true>(Xhi_g, Xlo_g, Xhi_g, Xlo_g, G_buf); }

__global__ void __launch_bounds__(256, 1)
gemm_d_k() { gemm_core<Tt, Oo, false>(Xhi_g, Xlo_g, Whi_g, Wlo_g, D_buf); }

// ============================================================
// Scan v3: 128 CTAs (single wave) x 256 threads, one row/thread.
// No y_s: each thread owns its row's observed slots via a 128-bit
// mask and writes outputs directly. Only Gs in smem; 2 syncs/chunk.
// ============================================================
__global__ void __launch_bounds__(256)
scan_kernel(const int* __restrict__ obs, float* __restrict__ out)
{
    __shared__ __align__(16) float Gs[Tt * CH];   // 32 KB

    const int tid = threadIdx.x;
    const int rg  = blockIdx.x;                   // 0..1
    const int b   = blockIdx.y;                   // 0..63
    const int o   = rg * 256 + tid;

    // 128-bit ownership mask over observed slots
    unsigned msk[4] = {0u, 0u, 0u, 0u};
    #pragma unroll 4
    for (int k = 0; k < NOBS; k++)
        if (__ldg(obs + k) == o) msk[k >> 5] |= 1u << (k & 31);
    const bool has_any = (msk[0] | msk[1] | msk[2] | msk[3]) != 0u;

    const float4* Gb4 = reinterpret_cast<const float4*>(G_buf + (size_t)b * Tt * Tt);
    const float* Db   = D_buf + (size_t)b * Tt * Oo + o;
    float*       Ub   = U_buf + (size_t)b * Tt * Oo + o;
    float*       outb = out   + (size_t)b * Tt * NOBS;

    float P = 1.0f;
    float uc[CH];

    for (int c = 0; c < NCH; c++) {
        const int t0   = c * CH;
        const int rows = t0 + CH;

        // prefetch D (independent; overlaps the staging barrier)
        float dv[CH];
        #pragma unroll
        for (int tl = 0; tl < CH; tl++) dv[tl] = Db[(t0 + tl) * Oo];

        __syncthreads();                 // all readers of Gs (prev chunk) done
        {
            float4* dst = reinterpret_cast<float4*>(Gs);
            for (int i = tid; i < rows * 8; i += 256) {
                const int j = i >> 3, q = i & 7;
                dst[i] = Gb4[j * (Tt / 4) + t0 / 4 + q];
            }
        }
        __syncthreads();                 // Gs staged

        // ---- history: H[tl] = sum_{j<t0} u_j * Gs[j][tl] (u: same-thread writes) ----
        u64 hacc[CH / 2];
        #pragma unroll
        for (int q = 0; q < CH / 2; q++) hacc[q] = 0;

        for (int j = 0; j < t0; j += 8) {
            float up[8];
            #pragma unroll
            for (int q = 0; q < 8; q++) up[q] = Ub[(j + q) * Oo];
            #pragma unroll
            for (int q = 0; q < 8; q++) {
                const u64 u2 = pack2(up[q], up[q]);
                const ulonglong2* grow = (const ulonglong2*)&Gs[(j + q) * CH];
                #pragma unroll
                for (int p = 0; p < CH / 4; p++) {
                    ulonglong2 gg = grow[p];
                    hacc[2 * p]     = ffma2(u2, gg.x, hacc[2 * p]);
                    hacc[2 * p + 1] = ffma2(u2, gg.y, hacc[2 * p + 1]);
                }
            }
        }
        float H[CH];
        #pragma unroll
        for (int q = 0; q < CH / 2; q++) unpack2(hacc[q], H[2 * q], H[2 * q + 1]);

        // ---- serial 32-step diagonal with direct observed writes ----
        #pragma unroll
        for (int tl = 0; tl < CH; tl++) {
            float S = H[tl];
            #pragma unroll
            for (int jl = 0; jl < tl; jl++)
                S = fmaf(uc[jl], Gs[(t0 + jl) * CH + tl], S);
            const float pre = P * (dv[tl] + S);
            const float y   = 1.0f / (1.0f + __expf(-pre));
            const float c1  = 1.0f - ETA * y * y;
            P *= c1;
            const float u = __fdividef(ETA * y, P);
            uc[tl] = u;
            Ub[(t0 + tl) * Oo] = u;

            if (has_any) {
                float* ot = outb + (size_t)(t0 + tl) * NOBS;
                #pragma unroll
                for (int w = 0; w < 4; w++) {
                    unsigned m = msk[w];
                    while (m) {
                        const int k = w * 32 + __ffs(m) - 1;
                        m &= m - 1;
                        ot[k] = y;
                    }
                }
            }
        }
    }
}

extern "C" void kernel_launch(void* const* d_in, const int* in_sizes, int n_in,
                              void* d_out, int out_size)
{
    const float* X  = (const float*)d_in[0];
    const float* Wi = (const float*)d_in[1];
    const int* obs  = (const int*)d_in[2];
    float* out      = (float*)d_out;

    cudaFuncSetAttribute(gemm_g_k, cudaFuncAttributeMaxDynamicSharedMemorySize, SM_TOTAL);
    cudaFuncSetAttribute(gemm_d_k, cudaFuncAttributeMaxDynamicSharedMemorySize, SM_TOTAL);

    const int nX4 = Bb * Tt * Ii / 4;
    const int nW4 = Bb * Oo * Ii / 4;
    split_x<<<(nX4 + 255) / 256, 256>>>(X);
    split_w<<<(nW4 + 255) / 256, 256>>>(Wi);

    gemm_g_k<<<dim3(Tt / 128, Tt / 128, Bb), 256, SM_TOTAL>>>();
    gemm_d_k<<<dim3(Oo / 128, Tt / 128, Bb), 256, SM_TOTAL>>>();

    scan_kernel<<<dim3(Oo / 256, Bb), 256>>>(obs, out);
}

// round 13
// speedup vs baseline: 1.3222x; 1.3222x over previous
#include <cuda_runtime.h>
#include <cuda_bf16.h>
#include <cstdint>

#define Bb   64
#define Tt   256
#define Ii   512
#define Oo   512
#define NOBS 128
#define ETA  0.01f
#define CH   32
#define NCH  (Tt / CH)

typedef unsigned long long u64;

// ---- scratch (static __device__, no allocs) ----
__device__ __align__(16) float G_buf[Bb * Tt * Tt];
__device__ __align__(16) float D_buf[Bb * Tt * Oo];
__device__ __align__(16) float U_buf[Bb * Tt * Oo];
__device__ __align__(16) __nv_bfloat16 Xhi_g[Bb * Tt * Ii];
__device__ __align__(16) __nv_bfloat16 Xlo_g[Bb * Tt * Ii];
__device__ __align__(16) __nv_bfloat16 Whi_g[Bb * Oo * Ii];
__device__ __align__(16) __nv_bfloat16 Wlo_g[Bb * Oo * Ii];

// ---- packed f32x2 helpers ----
__device__ __forceinline__ u64 pack2(float x, float y) {
    u64 r; asm("mov.b64 %0, {%1, %2};" : "=l"(r) : "f"(x), "f"(y)); return r;
}
__device__ __forceinline__ void unpack2(u64 v, float& x, float& y) {
    asm("mov.b64 {%0, %1}, %2;" : "=f"(x), "=f"(y) : "l"(v));
}
__device__ __forceinline__ u64 ffma2(u64 a, u64 b, u64 c) {
    u64 d; asm("fma.rn.f32x2 %0, %1, %2, %3;" : "=l"(d) : "l"(a), "l"(b), "l"(c)); return d;
}

// ---- mma.sync / cp.async helpers ----
__device__ __forceinline__ uint32_t smem_u32(const void* p) {
    uint32_t a;
    asm("{ .reg .u64 t; cvta.to.shared.u64 t, %1; cvt.u32.u64 %0, t; }" : "=r"(a) : "l"(p));
    return a;
}
__device__ __forceinline__ void ldsm4(uint32_t addr, uint32_t r[4]) {
    asm volatile("ldmatrix.sync.aligned.m8n8.x4.shared.b16 {%0,%1,%2,%3}, [%4];"
                 : "=r"(r[0]), "=r"(r[1]), "=r"(r[2]), "=r"(r[3]) : "r"(addr));
}
__device__ __forceinline__ void mma16816(float c[4], const uint32_t a[4],
                                         uint32_t b0, uint32_t b1) {
    asm volatile("mma.sync.aligned.m16n8k16.row.col.f32.bf16.bf16.f32 "
                 "{%0,%1,%2,%3}, {%4,%5,%6,%7}, {%8,%9}, {%0,%1,%2,%3};"
                 : "+f"(c[0]), "+f"(c[1]), "+f"(c[2]), "+f"(c[3])
                 : "r"(a[0]), "r"(a[1]), "r"(a[2]), "r"(a[3]), "r"(b0), "r"(b1));
}
#define CP_ASYNC16(dst, src) asm volatile("cp.async.cg.shared.global [%0], [%1], 16;" :: "r"(dst), "l"(src))
#define CP_COMMIT()          asm volatile("cp.async.commit_group;" ::: "memory")
#define CP_WAIT(n)           asm volatile("cp.async.wait_group %0;" :: "n"(n) : "memory")

#define SWZ(x) ((x) ^ (((x) >> 3) & 0x70))

// ============================================================
// bf16 hi/lo split conversion
// ============================================================
__device__ __forceinline__ void split_store(const float* __restrict__ src,
                                            __nv_bfloat16* __restrict__ hi,
                                            __nv_bfloat16* __restrict__ lo, int i)
{
    float4 v = reinterpret_cast<const float4*>(src)[i];
    __nv_bfloat16 h0 = __float2bfloat16(v.x), h1 = __float2bfloat16(v.y);
    __nv_bfloat16 h2 = __float2bfloat16(v.z), h3 = __float2bfloat16(v.w);
    __nv_bfloat16 l0 = __float2bfloat16(v.x - __bfloat162float(h0));
    __nv_bfloat16 l1 = __float2bfloat16(v.y - __bfloat162float(h1));
    __nv_bfloat16 l2 = __float2bfloat16(v.z - __bfloat162float(h2));
    __nv_bfloat16 l3 = __float2bfloat16(v.w - __bfloat162float(h3));
    reinterpret_cast<__nv_bfloat162*>(hi)[2 * i]     = __nv_bfloat162(h0, h1);
    reinterpret_cast<__nv_bfloat162*>(hi)[2 * i + 1] = __nv_bfloat162(h2, h3);
    reinterpret_cast<__nv_bfloat162*>(lo)[2 * i]     = __nv_bfloat162(l0, l1);
    reinterpret_cast<__nv_bfloat162*>(lo)[2 * i + 1] = __nv_bfloat162(l2, l3);
}

__global__ void __launch_bounds__(256)
split_x(const float* __restrict__ X)
{
    int i = blockIdx.x * 256 + threadIdx.x;
    if (i < Bb * Tt * Ii / 4) split_store(X, Xhi_g, Xlo_g, i);
}

__global__ void __launch_bounds__(256)
split_w(const float* __restrict__ W)
{
    int i = blockIdx.x * 256 + threadIdx.x;
    if (i < Bb * Oo * Ii / 4) split_store(W, Whi_g, Wlo_g, i);
}

// ============================================================
// mma.sync bf16 3-term-split GEMM, 128x128 tile/CTA, K=512, NT.
// 3-stage cp.async pipeline (prefetch distance 2). 3 x 64 KB smem.
// ============================================================
#define KC       64
#define NKC      (Ii / KC)
#define SM_TILE  16384
#define SM_STAGE (4 * SM_TILE)       // 64 KB
#define SM_TOTAL (3 * SM_STAGE)      // 192 KB

template<int M, int N, bool TRI>
__device__ __forceinline__ void gemm_core(const __nv_bfloat16* __restrict__ AH,
                                          const __nv_bfloat16* __restrict__ AL,
                                          const __nv_bfloat16* __restrict__ BH,
                                          const __nv_bfloat16* __restrict__ BL,
                                          float* __restrict__ Cg)
{
    const int nx = blockIdx.x, my = blockIdx.y, b = blockIdx.z;
    if (TRI && my > nx) return;

    extern __shared__ __align__(1024) char smem[];
    const uint32_t sb = smem_u32(smem);
    const int tid = threadIdx.x;
    const int wid = tid >> 5;
    const int l   = tid & 31;

    const int warp_m = wid & 1;
    const int warp_n = wid >> 1;

    const __nv_bfloat16* gbase[4];
    gbase[0] = AH + ((size_t)b * M + my * 128) * Ii;
    gbase[1] = AL + ((size_t)b * M + my * 128) * Ii;
    gbase[2] = BH + ((size_t)b * N + nx * 128) * Ii;
    gbase[3] = BL + ((size_t)b * N + nx * 128) * Ii;

    int  s_arr[16], s_rw[16], s_un[16];
    uint32_t s_dst[16];
    #pragma unroll
    for (int i = 0; i < 16; i++) {
        const int u = tid + 256 * i;
        s_arr[i] = u >> 10;
        const int rem = u & 1023;
        s_rw[i] = rem >> 3;
        s_un[i] = rem & 7;
        s_dst[i] = (uint32_t)(s_arr[i] * SM_TILE + SWZ(s_rw[i] * 128 + s_un[i] * 16));
    }

    const int g = l >> 3, r = l & 7;
    const uint32_t aoff = (uint32_t)(warp_m * 64 + (g & 1) * 8 + r) * 128;
    const uint32_t akb  = (uint32_t)((g >> 1) * 16);
    const uint32_t boff = (uint32_t)(warp_n * 32 + (g >> 1) * 8 + r) * 128;
    const uint32_t bkb  = (uint32_t)((g & 1) * 16);
    const uint32_t lxor = (uint32_t)(r << 4);

    float c[4][4][4];
    #pragma unroll
    for (int mt = 0; mt < 4; mt++)
        #pragma unroll
        for (int nt = 0; nt < 4; nt++)
            #pragma unroll
            for (int q = 0; q < 4; q++) c[mt][nt][q] = 0.0f;

    // prologue: issue chunks 0 and 1 (stages 0, 1)
    #pragma unroll
    for (int pc = 0; pc < 2; pc++) {
        const uint32_t sbuf = sb + (uint32_t)(pc * SM_STAGE);
        const int koff = pc * KC;
        #pragma unroll
        for (int i = 0; i < 16; i++) {
            const __nv_bfloat16* src =
                gbase[s_arr[i]] + (size_t)s_rw[i] * Ii + koff + s_un[i] * 8;
            CP_ASYNC16(sbuf + s_dst[i], src);
        }
        CP_COMMIT();
    }

    int stage = 0;
    for (int ck = 0; ck < NKC; ck++) {
        const uint32_t buf = sb + (uint32_t)(stage * SM_STAGE);

        if (ck + 2 < NKC) {
            // refill the stage consumed two iterations ago
            const int ns = (stage + 2) % 3;
            const uint32_t nbuf = sb + (uint32_t)(ns * SM_STAGE);
            const int koff = (ck + 2) * KC;
            #pragma unroll
            for (int i = 0; i < 16; i++) {
                const __nv_bfloat16* src =
                    gbase[s_arr[i]] + (size_t)s_rw[i] * Ii + koff + s_un[i] * 8;
                CP_ASYNC16(nbuf + s_dst[i], src);
            }
            CP_COMMIT();
            CP_WAIT(2);          // chunk ck's group complete
        } else if (ck + 1 < NKC) {
            CP_WAIT(1);
        } else {
            CP_WAIT(0);
        }
        __syncthreads();

        const uint32_t As_hi = buf;
        const uint32_t As_lo = buf + SM_TILE;
        const uint32_t Bs_hi = buf + 2 * SM_TILE;
        const uint32_t Bs_lo = buf + 3 * SM_TILE;

        #pragma unroll
        for (int ks = 0; ks < 4; ks++) {
            const uint32_t kb = (uint32_t)(ks * 32);

            uint32_t bh[4][2], bl[4][2];
            #pragma unroll
            for (int nt2 = 0; nt2 < 2; nt2++) {
                uint32_t t4[4];
                const uint32_t badd = boff + nt2 * 2048 + ((kb + bkb) ^ lxor);
                ldsm4(Bs_hi + badd, t4);
                bh[2 * nt2][0] = t4[0]; bh[2 * nt2][1] = t4[1];
                bh[2 * nt2 + 1][0] = t4[2]; bh[2 * nt2 + 1][1] = t4[3];
                ldsm4(Bs_lo + badd, t4);
                bl[2 * nt2][0] = t4[0]; bl[2 * nt2][1] = t4[1];
                bl[2 * nt2 + 1][0] = t4[2]; bl[2 * nt2 + 1][1] = t4[3];
            }

            #pragma unroll
            for (int mt = 0; mt < 4; mt++) {
                const uint32_t aadd = aoff + mt * 2048 + ((kb + akb) ^ lxor);
                uint32_t a4[4];
                ldsm4(As_hi + aadd, a4);
                #pragma unroll
                for (int nt = 0; nt < 4; nt++) {
                    mma16816(c[mt][nt], a4, bh[nt][0], bh[nt][1]);
                    mma16816(c[mt][nt], a4, bl[nt][0], bl[nt][1]);
                }
                ldsm4(As_lo + aadd, a4);
                #pragma unroll
                for (int nt = 0; nt < 4; nt++)
                    mma16816(c[mt][nt], a4, bh[nt][0], bh[nt][1]);
            }
        }
        __syncthreads();   // all readers done before this stage is refilled
        stage = (stage + 1) % 3;
    }

    float* Crow = Cg + ((size_t)b * M + my * 128) * N + nx * 128;
    const int qr = l >> 2, qc = l & 3;
    #pragma unroll
    for (int mt = 0; mt < 4; mt++) {
        const int m0 = warp_m * 64 + mt * 16;
        #pragma unroll
        for (int nt = 0; nt < 4; nt++) {
            const int n0 = warp_n * 32 + nt * 8 + 2 * qc;
            *reinterpret_cast<float2*>(&Crow[(size_t)(m0 + qr) * N + n0]) =
                make_float2(c[mt][nt][0], c[mt][nt][1]);
            *reinterpret_cast<float2*>(&Crow[(size_t)(m0 + qr + 8) * N + n0]) =
                make_float2(c[mt][nt][2], c[mt][nt][3]);
        }
    }
}

__global__ void __launch_bounds__(256, 1)
gemm_g_k() { gemm_core<Tt, Tt, true>(Xhi_g, Xlo_g, Xhi_g, Xlo_g, G_buf); }

__global__ void __launch_bounds__(256, 1)
gemm_d_k() { gemm_core<Tt, Oo, false>(Xhi_g, Xlo_g, Whi_g, Wlo_g, D_buf); }

// ============================================================
// Scan (R10 structure, proven 307 us run) + pipelined u-loads.
// ============================================================
__global__ void __launch_bounds__(128, 4)
scan_kernel(const int* __restrict__ obs, float* __restrict__ out)
{
    __shared__ __align__(16) float Gs[Tt * CH];   // 32 KB
    __shared__ float y_s[CH * 128];               // 16 KB

    const int tid  = threadIdx.x;
    const int rg   = blockIdx.x;
    const int b    = blockIdx.y;
    const int orow = rg * 128 + tid;

    const int  slot_o    = obs[tid];
    const bool have_slot = ((slot_o >> 7) == rg);
    const int  slot_lrow = slot_o & 127;

    const float4* Gb4 = reinterpret_cast<const float4*>(G_buf + (size_t)b * Tt * Tt);
    const float* Db   = D_buf + (size_t)b * Tt * Oo + orow;
    float*       Ub   = U_buf + (size_t)b * Tt * Oo + orow;
    float*       outb = out   + (size_t)b * Tt * NOBS;

    float P = 1.0f;
    float uc[CH];

    for (int c = 0; c < NCH; c++) {
        const int t0   = c * CH;
        const int rows = t0 + CH;

        // prefetch this chunk's D values (independent LDGs, MLP=32)
        float dv[CH];
        #pragma unroll
        for (int tl = 0; tl < CH; tl++) dv[tl] = Db[(t0 + tl) * Oo];

        __syncthreads();
        // stage Gs[j][tl] = G[b][j][t0+tl], j < rows, as float4
        {
            float4* dst = reinterpret_cast<float4*>(Gs);
            for (int i = tid; i < rows * 8; i += 128) {
                const int j = i >> 3, q = i & 7;
                dst[i] = Gb4[j * (Tt / 4) + t0 / 4 + q];
            }
        }
        __syncthreads();

        // ---- history: H[tl] = sum_{j<t0} u_j * Gs[j][tl] ----
        // u loads software-pipelined: prefetch block j+8 while FMA-ing block j.
        u64 hacc[CH / 2];
        #pragma unroll
        for (int q = 0; q < CH / 2; q++) hacc[q] = 0;

        if (t0 > 0) {
            float up[8], un[8];
            #pragma unroll
            for (int q = 0; q < 8; q++) up[q] = Ub[q * Oo];

            for (int j = 0; j < t0; j += 8) {
                if (j + 8 < t0) {
                    #pragma unroll
                    for (int q = 0; q < 8; q++) un[q] = Ub[(j + 8 + q) * Oo];
                }
                #pragma unroll
                for (int q = 0; q < 8; q++) {
                    const u64 u2 = pack2(up[q], up[q]);
                    const ulonglong2* grow = (const ulonglong2*)&Gs[(j + q) * CH];
                    #pragma unroll
                    for (int p = 0; p < CH / 4; p++) {
                        ulonglong2 gg = grow[p];
                        hacc[2 * p]     = ffma2(u2, gg.x, hacc[2 * p]);
                        hacc[2 * p + 1] = ffma2(u2, gg.y, hacc[2 * p + 1]);
                    }
                }
                #pragma unroll
                for (int q = 0; q < 8; q++) up[q] = un[q];
            }
        }
        float H[CH];
        #pragma unroll
        for (int q = 0; q < CH / 2; q++) unpack2(hacc[q], H[2 * q], H[2 * q + 1]);

        // ---- serial 32-step diagonal (D already in regs) ----
        #pragma unroll
        for (int tl = 0; tl < CH; tl++) {
            float S = H[tl];
            #pragma unroll
            for (int jl = 0; jl < tl; jl++)
                S = fmaf(uc[jl], Gs[(t0 + jl) * CH + tl], S);
            const float pre = P * (dv[tl] + S);
            const float y   = 1.0f / (1.0f + __expf(-pre));
            const float c1  = 1.0f - ETA * y * y;
            P *= c1;
            const float u = __fdividef(ETA * y, P);
            uc[tl] = u;
            Ub[(t0 + tl) * Oo]  = u;
            y_s[tl * 128 + tid] = y;
        }
        __syncthreads();

        if (have_slot) {
            #pragma unroll 4
            for (int tl = 0; tl < CH; tl++)
                outb[(t0 + tl) * NOBS + tid] = y_s[tl * 128 + slot_lrow];
        }
    }
}

extern "C" void kernel_launch(void* const* d_in, const int* in_sizes, int n_in,
                              void* d_out, int out_size)
{
    const float* X  = (const float*)d_in[0];
    const float* Wi = (const float*)d_in[1];
    const int* obs  = (const int*)d_in[2];
    float* out      = (float*)d_out;

    cudaFuncSetAttribute(gemm_g_k, cudaFuncAttributeMaxDynamicSharedMemorySize, SM_TOTAL);
    cudaFuncSetAttribute(gemm_d_k, cudaFuncAttributeMaxDynamicSharedMemorySize, SM_TOTAL);

    const int nX4 = Bb * Tt * Ii / 4;
    const int nW4 = Bb * Oo * Ii / 4;
    split_x<<<(nX4 + 255) / 256, 256>>>(X);
    split_w<<<(nW4 + 255) / 256, 256>>>(Wi);

    gemm_g_k<<<dim3(Tt / 128, Tt / 128, Bb), 256, SM_TOTAL>>>();
    gemm_d_k<<<dim3(Oo / 128, Tt / 128, Bb), 256, SM_TOTAL>>>();

    scan_kernel<<<dim3(Oo / 128, Bb), 128>>>(obs, out);
}

// round 14
// speedup vs baseline: 1.3946x; 1.0547x over previous
#include <cuda_runtime.h>
#include <cuda_bf16.h>
#include <cstdint>

#define Bb   64
#define Tt   256
#define Ii   512
#define Oo   512
#define NOBS 128
#define ETA  0.01f
#define CH   32
#define NCH  (Tt / CH)

typedef unsigned long long u64;

// ---- scratch (static __device__, no allocs) ----
__device__ __align__(16) float G_buf[Bb * Tt * Tt];
__device__ __align__(16) float D_buf[Bb * Tt * Oo];
__device__ __align__(16) float U_buf[Bb * Tt * Oo];
__device__ __align__(16) __nv_bfloat16 Xhi_g[Bb * Tt * Ii];
__device__ __align__(16) __nv_bfloat16 Xlo_g[Bb * Tt * Ii];
__device__ __align__(16) __nv_bfloat16 Whi_g[Bb * Oo * Ii];
__device__ __align__(16) __nv_bfloat16 Wlo_g[Bb * Oo * Ii];

// ---- packed f32x2 helpers ----
__device__ __forceinline__ u64 pack2(float x, float y) {
    u64 r; asm("mov.b64 %0, {%1, %2};" : "=l"(r) : "f"(x), "f"(y)); return r;
}
__device__ __forceinline__ void unpack2(u64 v, float& x, float& y) {
    asm("mov.b64 {%0, %1}, %2;" : "=f"(x), "=f"(y) : "l"(v));
}
__device__ __forceinline__ u64 ffma2(u64 a, u64 b, u64 c) {
    u64 d; asm("fma.rn.f32x2 %0, %1, %2, %3;" : "=l"(d) : "l"(a), "l"(b), "l"(c)); return d;
}

// ---- mma.sync / cp.async helpers ----
__device__ __forceinline__ uint32_t smem_u32(const void* p) {
    uint32_t a;
    asm("{ .reg .u64 t; cvta.to.shared.u64 t, %1; cvt.u32.u64 %0, t; }" : "=r"(a) : "l"(p));
    return a;
}
__device__ __forceinline__ void ldsm4(uint32_t addr, uint32_t r[4]) {
    asm volatile("ldmatrix.sync.aligned.m8n8.x4.shared.b16 {%0,%1,%2,%3}, [%4];"
                 : "=r"(r[0]), "=r"(r[1]), "=r"(r[2]), "=r"(r[3]) : "r"(addr));
}
__device__ __forceinline__ void mma16816(float c[4], const uint32_t a[4],
                                         uint32_t b0, uint32_t b1) {
    asm volatile("mma.sync.aligned.m16n8k16.row.col.f32.bf16.bf16.f32 "
                 "{%0,%1,%2,%3}, {%4,%5,%6,%7}, {%8,%9}, {%0,%1,%2,%3};"
                 : "+f"(c[0]), "+f"(c[1]), "+f"(c[2]), "+f"(c[3])
                 : "r"(a[0]), "r"(a[1]), "r"(a[2]), "r"(a[3]), "r"(b0), "r"(b1));
}
#define CP_ASYNC16(dst, src) asm volatile("cp.async.cg.shared.global [%0], [%1], 16;" :: "r"(dst), "l"(src))
#define CP_COMMIT()          asm volatile("cp.async.commit_group;" ::: "memory")
#define CP_WAIT(n)           asm volatile("cp.async.wait_group %0;" :: "n"(n) : "memory")

#define SWZ(x) ((x) ^ (((x) >> 3) & 0x70))

// ============================================================
// bf16 hi/lo split conversion
// ============================================================
__device__ __forceinline__ void split_store(const float* __restrict__ src,
                                            __nv_bfloat16* __restrict__ hi,
                                            __nv_bfloat16* __restrict__ lo, int i)
{
    float4 v = reinterpret_cast<const float4*>(src)[i];
    __nv_bfloat16 h0 = __float2bfloat16(v.x), h1 = __float2bfloat16(v.y);
    __nv_bfloat16 h2 = __float2bfloat16(v.z), h3 = __float2bfloat16(v.w);
    __nv_bfloat16 l0 = __float2bfloat16(v.x - __bfloat162float(h0));
    __nv_bfloat16 l1 = __float2bfloat16(v.y - __bfloat162float(h1));
    __nv_bfloat16 l2 = __float2bfloat16(v.z - __bfloat162float(h2));
    __nv_bfloat16 l3 = __float2bfloat16(v.w - __bfloat162float(h3));
    reinterpret_cast<__nv_bfloat162*>(hi)[2 * i]     = __nv_bfloat162(h0, h1);
    reinterpret_cast<__nv_bfloat162*>(hi)[2 * i + 1] = __nv_bfloat162(h2, h3);
    reinterpret_cast<__nv_bfloat162*>(lo)[2 * i]     = __nv_bfloat162(l0, l1);
    reinterpret_cast<__nv_bfloat162*>(lo)[2 * i + 1] = __nv_bfloat162(l2, l3);
}

__global__ void __launch_bounds__(256)
split_x(const float* __restrict__ X)
{
    int i = blockIdx.x * 256 + threadIdx.x;
    if (i < Bb * Tt * Ii / 4) split_store(X, Xhi_g, Xlo_g, i);
}

__global__ void __launch_bounds__(256)
split_w(const float* __restrict__ W)
{
    int i = blockIdx.x * 256 + threadIdx.x;
    if (i < Bb * Oo * Ii / 4) split_store(W, Whi_g, Wlo_g, i);
}

// ============================================================
// mma.sync bf16 3-term-split GEMM, 128x128 tile/CTA, K=512, NT,
// 2-stage cp.async pipeline, 512 threads = 16 warps (4m x 4n),
// warp tile 32x32. Same smem layout/swizzle as the 307 us run.
// ============================================================
#define KC       64
#define NKC      (Ii / KC)
#define SM_TILE  16384
#define SM_STAGE (4 * SM_TILE)   // 64 KB
#define SM_TOTAL (2 * SM_STAGE)  // 128 KB
#define GTHREADS 512

template<int M, int N, bool TRI>
__device__ __forceinline__ void gemm_core(const __nv_bfloat16* __restrict__ AH,
                                          const __nv_bfloat16* __restrict__ AL,
                                          const __nv_bfloat16* __restrict__ BH,
                                          const __nv_bfloat16* __restrict__ BL,
                                          float* __restrict__ Cg)
{
    const int nx = blockIdx.x, my = blockIdx.y, b = blockIdx.z;
    if (TRI && my > nx) return;

    extern __shared__ __align__(1024) char smem[];
    const uint32_t sb = smem_u32(smem);
    const int tid = threadIdx.x;
    const int wid = tid >> 5;
    const int l   = tid & 31;

    const int warp_m = wid & 3;        // 0..3 (32-row slab)
    const int warp_n = wid >> 2;       // 0..3 (32-col slab)

    const __nv_bfloat16* gbase[4];
    gbase[0] = AH + ((size_t)b * M + my * 128) * Ii;
    gbase[1] = AL + ((size_t)b * M + my * 128) * Ii;
    gbase[2] = BH + ((size_t)b * N + nx * 128) * Ii;
    gbase[3] = BL + ((size_t)b * N + nx * 128) * Ii;

    // per-thread staging pattern: 8 units of 16 B (512 threads x 8 = 4096)
    int  s_arr[8], s_rw[8], s_un[8];
    uint32_t s_dst[8];
    #pragma unroll
    for (int i = 0; i < 8; i++) {
        const int u = tid + GTHREADS * i;
        s_arr[i] = u >> 10;
        const int rem = u & 1023;
        s_rw[i] = rem >> 3;
        s_un[i] = rem & 7;
        s_dst[i] = (uint32_t)(s_arr[i] * SM_TILE + SWZ(s_rw[i] * 128 + s_un[i] * 16));
    }

    // ldmatrix per-lane addressing (SW128: xor mask reduces to r<<4)
    const int g = l >> 3, r = l & 7;
    const uint32_t aoff = (uint32_t)(warp_m * 32 + (g & 1) * 8 + r) * 128;
    const uint32_t akb  = (uint32_t)((g >> 1) * 16);
    const uint32_t boff = (uint32_t)(warp_n * 32 + (g >> 1) * 8 + r) * 128;
    const uint32_t bkb  = (uint32_t)((g & 1) * 16);
    const uint32_t lxor = (uint32_t)(r << 4);

    float c[2][4][4];
    #pragma unroll
    for (int mt = 0; mt < 2; mt++)
        #pragma unroll
        for (int nt = 0; nt < 4; nt++)
            #pragma unroll
            for (int q = 0; q < 4; q++) c[mt][nt][q] = 0.0f;

    // ---- prologue: stage chunk 0 into buf 0 ----
    #pragma unroll
    for (int i = 0; i < 8; i++) {
        const __nv_bfloat16* src = gbase[s_arr[i]] + (size_t)s_rw[i] * Ii + s_un[i] * 8;
        CP_ASYNC16(sb + s_dst[i], src);
    }
    CP_COMMIT();

    for (int ck = 0; ck < NKC; ck++) {
        const uint32_t buf = sb + (uint32_t)((ck & 1) * SM_STAGE);

        if (ck + 1 < NKC) {
            const uint32_t nbuf = (uint32_t)(((ck + 1) & 1) * SM_STAGE);
            const int koff = (ck + 1) * KC;
            #pragma unroll
            for (int i = 0; i < 8; i++) {
                const __nv_bfloat16* src =
                    gbase[s_arr[i]] + (size_t)s_rw[i] * Ii + koff + s_un[i] * 8;
                CP_ASYNC16(sb + nbuf + s_dst[i], src);
            }
            CP_COMMIT();
            CP_WAIT(1);
        } else {
            CP_WAIT(0);
        }
        __syncthreads();

        const uint32_t As_hi = buf;
        const uint32_t As_lo = buf + SM_TILE;
        const uint32_t Bs_hi = buf + 2 * SM_TILE;
        const uint32_t Bs_lo = buf + 3 * SM_TILE;

        #pragma unroll
        for (int ks = 0; ks < 4; ks++) {
            const uint32_t kb = (uint32_t)(ks * 32);

            // B frags (32 cols = 2 x ldsm.x4 per hi/lo)
            uint32_t bh[4][2], bl[4][2];
            #pragma unroll
            for (int nt2 = 0; nt2 < 2; nt2++) {
                uint32_t t4[4];
                const uint32_t badd = boff + nt2 * 2048 + ((kb + bkb) ^ lxor);
                ldsm4(Bs_hi + badd, t4);
                bh[2 * nt2][0] = t4[0]; bh[2 * nt2][1] = t4[1];
                bh[2 * nt2 + 1][0] = t4[2]; bh[2 * nt2 + 1][1] = t4[3];
                ldsm4(Bs_lo + badd, t4);
                bl[2 * nt2][0] = t4[0]; bl[2 * nt2][1] = t4[1];
                bl[2 * nt2 + 1][0] = t4[2]; bl[2 * nt2 + 1][1] = t4[3];
            }

            // A frags (32 rows = 2 x 16), hi then lo
            #pragma unroll
            for (int mt = 0; mt < 2; mt++) {
                const uint32_t aadd = aoff + mt * 2048 + ((kb + akb) ^ lxor);
                uint32_t a4[4];
                ldsm4(As_hi + aadd, a4);
                #pragma unroll
                for (int nt = 0; nt < 4; nt++) {
                    mma16816(c[mt][nt], a4, bh[nt][0], bh[nt][1]);
                    mma16816(c[mt][nt], a4, bl[nt][0], bl[nt][1]);
                }
                ldsm4(As_lo + aadd, a4);
                #pragma unroll
                for (int nt = 0; nt < 4; nt++)
                    mma16816(c[mt][nt], a4, bh[nt][0], bh[nt][1]);
            }
        }
        __syncthreads();   // compute on buf done before it is refilled
    }

    // ---- epilogue: direct fragment stores ----
    float* Crow = Cg + ((size_t)b * M + my * 128) * N + nx * 128;
    const int qr = l >> 2, qc = l & 3;
    #pragma unroll
    for (int mt = 0; mt < 2; mt++) {
        const int m0 = warp_m * 32 + mt * 16;
        #pragma unroll
        for (int nt = 0; nt < 4; nt++) {
            const int n0 = warp_n * 32 + nt * 8 + 2 * qc;
            *reinterpret_cast<float2*>(&Crow[(size_t)(m0 + qr) * N + n0]) =
                make_float2(c[mt][nt][0], c[mt][nt][1]);
            *reinterpret_cast<float2*>(&Crow[(size_t)(m0 + qr + 8) * N + n0]) =
                make_float2(c[mt][nt][2], c[mt][nt][3]);
        }
    }
}

__global__ void __launch_bounds__(GTHREADS, 1)
gemm_g_k() { gemm_core<Tt, Tt, true>(Xhi_g, Xlo_g, Xhi_g, Xlo_g, G_buf); }

__global__ void __launch_bounds__(GTHREADS, 1)
gemm_d_k() { gemm_core<Tt, Oo, false>(Xhi_g, Xlo_g, Whi_g, Wlo_g, D_buf); }

// ============================================================
// Scan (exact R10 structure: proven 307 us run)
// ============================================================
__global__ void __launch_bounds__(128, 4)
scan_kernel(const int* __restrict__ obs, float* __restrict__ out)
{
    __shared__ __align__(16) float Gs[Tt * CH];   // 32 KB
    __shared__ float y_s[CH * 128];               // 16 KB

    const int tid  = threadIdx.x;
    const int rg   = blockIdx.x;
    const int b    = blockIdx.y;
    const int orow = rg * 128 + tid;

    const int  slot_o    = obs[tid];
    const bool have_slot = ((slot_o >> 7) == rg);
    const int  slot_lrow = slot_o & 127;

    const float4* Gb4 = reinterpret_cast<const float4*>(G_buf + (size_t)b * Tt * Tt);
    const float* Db   = D_buf + (size_t)b * Tt * Oo + orow;
    float*       Ub   = U_buf + (size_t)b * Tt * Oo + orow;
    float*       outb = out   + (size_t)b * Tt * NOBS;

    float P = 1.0f;
    float uc[CH];

    for (int c = 0; c < NCH; c++) {
        const int t0   = c * CH;
        const int rows = t0 + CH;

        // prefetch this chunk's D values (independent LDGs, MLP=32)
        float dv[CH];
        #pragma unroll
        for (int tl = 0; tl < CH; tl++) dv[tl] = Db[(t0 + tl) * Oo];

        __syncthreads();
        // stage Gs[j][tl] = G[b][j][t0+tl], j < rows, as float4
        {
            float4* dst = reinterpret_cast<float4*>(Gs);
            for (int i = tid; i < rows * 8; i += 128) {
                const int j = i >> 3, q = i & 7;
                dst[i] = Gb4[j * (Tt / 4) + t0 / 4 + q];
            }
        }
        __syncthreads();

        // ---- history: H[tl] = sum_{j<t0} u_j * Gs[j][tl], MLP-8 u loads ----
        u64 hacc[CH / 2];
        #pragma unroll
        for (int q = 0; q < CH / 2; q++) hacc[q] = 0;

        for (int j = 0; j < t0; j += 8) {
            float up[8];
            #pragma unroll
            for (int q = 0; q < 8; q++) up[q] = Ub[(j + q) * Oo];
            #pragma unroll
            for (int q = 0; q < 8; q++) {
                const u64 u2 = pack2(up[q], up[q]);
                const ulonglong2* grow = (const ulonglong2*)&Gs[(j + q) * CH];
                #pragma unroll
                for (int p = 0; p < CH / 4; p++) {
                    ulonglong2 gg = grow[p];
                    hacc[2 * p]     = ffma2(u2, gg.x, hacc[2 * p]);
                    hacc[2 * p + 1] = ffma2(u2, gg.y, hacc[2 * p + 1]);
                }
            }
        }
        float H[CH];
        #pragma unroll
        for (int q = 0; q < CH / 2; q++) unpack2(hacc[q], H[2 * q], H[2 * q + 1]);

        // ---- serial 32-step diagonal (D already in regs) ----
        #pragma unroll
        for (int tl = 0; tl < CH; tl++) {
            float S = H[tl];
            #pragma unroll
            for (int jl = 0; jl < tl; jl++)
                S = fmaf(uc[jl], Gs[(t0 + jl) * CH + tl], S);
            const float pre = P * (dv[tl] + S);
            const float y   = 1.0f / (1.0f + __expf(-pre));
            const float c1  = 1.0f - ETA * y * y;
            P *= c1;
            const float u = __fdividef(ETA * y, P);
            uc[tl] = u;
            Ub[(t0 + tl) * Oo]  = u;
            y_s[tl * 128 + tid] = y;
        }
        __syncthreads();

        if (have_slot) {
            #pragma unroll 4
            for (int tl = 0; tl < CH; tl++)
                outb[(t0 + tl) * NOBS + tid] = y_s[tl * 128 + slot_lrow];
        }
    }
}

extern "C" void kernel_launch(void* const* d_in, const int* in_sizes, int n_in,
                              void* d_out, int out_size)
{
    const float* X  = (const float*)d_in[0];
    const float* Wi = (const float*)d_in[1];
    const int* obs  = (const int*)d_in[2];
    float* out      = (float*)d_out;

    cudaFuncSetAttribute(gemm_g_k, cudaFuncAttributeMaxDynamicSharedMemorySize, SM_TOTAL);
    cudaFuncSetAttribute(gemm_d_k, cudaFuncAttributeMaxDynamicSharedMemorySize, SM_TOTAL);

    const int nX4 = Bb * Tt * Ii / 4;
    const int nW4 = Bb * Oo * Ii / 4;
    split_x<<<(nX4 + 255) / 256, 256>>>(X);
    split_w<<<(nW4 + 255) / 256, 256>>>(Wi);

    gemm_g_k<<<dim3(Tt / 128, Tt / 128, Bb), GTHREADS, SM_TOTAL>>>();
    gemm_d_k<<<dim3(Oo / 128, Tt / 128, Bb), GTHREADS, SM_TOTAL>>>();

    scan_kernel<<<dim3(Oo / 128, Bb), 128>>>(obs, out);
}

// round 15
// speedup vs baseline: 1.5231x; 1.0922x over previous
#include <cuda_runtime.h>
#include <cuda_bf16.h>
#include <cstdint>

#define Bb   64
#define Tt   256
#define Ii   512
#define Oo   512
#define NOBS 128
#define ETA  0.01f
#define CH   32
#define NCH  (Tt / CH)

typedef unsigned long long u64;

// ---- scratch (static __device__, no allocs) ----
__device__ __align__(16) float G_buf[Bb * Tt * Tt];
__device__ __align__(16) float D_buf[Bb * Tt * Oo];
__device__ __align__(16) float U_buf[Bb * Tt * Oo];
__device__ __align__(16) __nv_bfloat16 Xhi_g[Bb * Tt * Ii];
__device__ __align__(16) __nv_bfloat16 Xlo_g[Bb * Tt * Ii];
__device__ __align__(16) __nv_bfloat16 Whi_g[Bb * Oo * Ii];
__device__ __align__(16) __nv_bfloat16 Wlo_g[Bb * Oo * Ii];

// ---- packed f32x2 helpers ----
__device__ __forceinline__ u64 pack2(float x, float y) {
    u64 r; asm("mov.b64 %0, {%1, %2};" : "=l"(r) : "f"(x), "f"(y)); return r;
}
__device__ __forceinline__ void unpack2(u64 v, float& x, float& y) {
    asm("mov.b64 {%0, %1}, %2;" : "=f"(x), "=f"(y) : "l"(v));
}
__device__ __forceinline__ u64 ffma2(u64 a, u64 b, u64 c) {
    u64 d; asm("fma.rn.f32x2 %0, %1, %2, %3;" : "=l"(d) : "l"(a), "l"(b), "l"(c)); return d;
}

// ---- mma.sync / cp.async helpers ----
__device__ __forceinline__ uint32_t smem_u32(const void* p) {
    uint32_t a;
    asm("{ .reg .u64 t; cvta.to.shared.u64 t, %1; cvt.u32.u64 %0, t; }" : "=r"(a) : "l"(p));
    return a;
}
__device__ __forceinline__ void ldsm4(uint32_t addr, uint32_t r[4]) {
    asm volatile("ldmatrix.sync.aligned.m8n8.x4.shared.b16 {%0,%1,%2,%3}, [%4];"
                 : "=r"(r[0]), "=r"(r[1]), "=r"(r[2]), "=r"(r[3]) : "r"(addr));
}
__device__ __forceinline__ void mma16816(float c[4], const uint32_t a[4],
                                         uint32_t b0, uint32_t b1) {
    asm volatile("mma.sync.aligned.m16n8k16.row.col.f32.bf16.bf16.f32 "
                 "{%0,%1,%2,%3}, {%4,%5,%6,%7}, {%8,%9}, {%0,%1,%2,%3};"
                 : "+f"(c[0]), "+f"(c[1]), "+f"(c[2]), "+f"(c[3])
                 : "r"(a[0]), "r"(a[1]), "r"(a[2]), "r"(a[3]), "r"(b0), "r"(b1));
}
#define CP_ASYNC16(dst, src) asm volatile("cp.async.cg.shared.global [%0], [%1], 16;" :: "r"(dst), "l"(src))
#define CP_COMMIT()          asm volatile("cp.async.commit_group;" ::: "memory")
#define CP_WAIT(n)           asm volatile("cp.async.wait_group %0;" :: "n"(n) : "memory")

#define SWZ(x) ((x) ^ (((x) >> 3) & 0x70))

// ============================================================
// bf16 hi/lo split conversion
// ============================================================
__device__ __forceinline__ void split_store(const float* __restrict__ src,
                                            __nv_bfloat16* __restrict__ hi,
                                            __nv_bfloat16* __restrict__ lo, int i)
{
    float4 v = reinterpret_cast<const float4*>(src)[i];
    __nv_bfloat16 h0 = __float2bfloat16(v.x), h1 = __float2bfloat16(v.y);
    __nv_bfloat16 h2 = __float2bfloat16(v.z), h3 = __float2bfloat16(v.w);
    __nv_bfloat16 l0 = __float2bfloat16(v.x - __bfloat162float(h0));
    __nv_bfloat16 l1 = __float2bfloat16(v.y - __bfloat162float(h1));
    __nv_bfloat16 l2 = __float2bfloat16(v.z - __bfloat162float(h2));
    __nv_bfloat16 l3 = __float2bfloat16(v.w - __bfloat162float(h3));
    reinterpret_cast<__nv_bfloat162*>(hi)[2 * i]     = __nv_bfloat162(h0, h1);
    reinterpret_cast<__nv_bfloat162*>(hi)[2 * i + 1] = __nv_bfloat162(h2, h3);
    reinterpret_cast<__nv_bfloat162*>(lo)[2 * i]     = __nv_bfloat162(l0, l1);
    reinterpret_cast<__nv_bfloat162*>(lo)[2 * i + 1] = __nv_bfloat162(l2, l3);
}

__global__ void __launch_bounds__(256)
split_x(const float* __restrict__ X)
{
    int i = blockIdx.x * 256 + threadIdx.x;
    if (i < Bb * Tt * Ii / 4) split_store(X, Xhi_g, Xlo_g, i);
}

__global__ void __launch_bounds__(256)
split_w(const float* __restrict__ W)
{
    int i = blockIdx.x * 256 + threadIdx.x;
    if (i < Bb * Oo * Ii / 4) split_store(W, Whi_g, Wlo_g, i);
}

// ============================================================
// mma.sync bf16 3-term-split GEMM (byte-identical to R14: 301 us run)
// 512 threads = 16 warps (4m x 4n), warp tile 32x32, 2-stage cp.async.
// ============================================================
#define KC       64
#define NKC      (Ii / KC)
#define SM_TILE  16384
#define SM_STAGE (4 * SM_TILE)   // 64 KB
#define SM_TOTAL (2 * SM_STAGE)  // 128 KB
#define GTHREADS 512

template<int M, int N, bool TRI>
__device__ __forceinline__ void gemm_core(const __nv_bfloat16* __restrict__ AH,
                                          const __nv_bfloat16* __restrict__ AL,
                                          const __nv_bfloat16* __restrict__ BH,
                                          const __nv_bfloat16* __restrict__ BL,
                                          float* __restrict__ Cg)
{
    const int nx = blockIdx.x, my = blockIdx.y, b = blockIdx.z;
    if (TRI && my > nx) return;

    extern __shared__ __align__(1024) char smem[];
    const uint32_t sb = smem_u32(smem);
    const int tid = threadIdx.x;
    const int wid = tid >> 5;
    const int l   = tid & 31;

    const int warp_m = wid & 3;
    const int warp_n = wid >> 2;

    const __nv_bfloat16* gbase[4];
    gbase[0] = AH + ((size_t)b * M + my * 128) * Ii;
    gbase[1] = AL + ((size_t)b * M + my * 128) * Ii;
    gbase[2] = BH + ((size_t)b * N + nx * 128) * Ii;
    gbase[3] = BL + ((size_t)b * N + nx * 128) * Ii;

    int  s_arr[8], s_rw[8], s_un[8];
    uint32_t s_dst[8];
    #pragma unroll
    for (int i = 0; i < 8; i++) {
        const int u = tid + GTHREADS * i;
        s_arr[i] = u >> 10;
        const int rem = u & 1023;
        s_rw[i] = rem >> 3;
        s_un[i] = rem & 7;
        s_dst[i] = (uint32_t)(s_arr[i] * SM_TILE + SWZ(s_rw[i] * 128 + s_un[i] * 16));
    }

    const int g = l >> 3, r = l & 7;
    const uint32_t aoff = (uint32_t)(warp_m * 32 + (g & 1) * 8 + r) * 128;
    const uint32_t akb  = (uint32_t)((g >> 1) * 16);
    const uint32_t boff = (uint32_t)(warp_n * 32 + (g >> 1) * 8 + r) * 128;
    const uint32_t bkb  = (uint32_t)((g & 1) * 16);
    const uint32_t lxor = (uint32_t)(r << 4);

    float c[2][4][4];
    #pragma unroll
    for (int mt = 0; mt < 2; mt++)
        #pragma unroll
        for (int nt = 0; nt < 4; nt++)
            #pragma unroll
            for (int q = 0; q < 4; q++) c[mt][nt][q] = 0.0f;

    #pragma unroll
    for (int i = 0; i < 8; i++) {
        const __nv_bfloat16* src = gbase[s_arr[i]] + (size_t)s_rw[i] * Ii + s_un[i] * 8;
        CP_ASYNC16(sb + s_dst[i], src);
    }
    CP_COMMIT();

    for (int ck = 0; ck < NKC; ck++) {
        const uint32_t buf = sb + (uint32_t)((ck & 1) * SM_STAGE);

        if (ck + 1 < NKC) {
            const uint32_t nbuf = (uint32_t)(((ck + 1) & 1) * SM_STAGE);
            const int koff = (ck + 1) * KC;
            #pragma unroll
            for (int i = 0; i < 8; i++) {
                const __nv_bfloat16* src =
                    gbase[s_arr[i]] + (size_t)s_rw[i] * Ii + koff + s_un[i] * 8;
                CP_ASYNC16(sb + nbuf + s_dst[i], src);
            }
            CP_COMMIT();
            CP_WAIT(1);
        } else {
            CP_WAIT(0);
        }
        __syncthreads();

        const uint32_t As_hi = buf;
        const uint32_t As_lo = buf + SM_TILE;
        const uint32_t Bs_hi = buf + 2 * SM_TILE;
        const uint32_t Bs_lo = buf + 3 * SM_TILE;

        #pragma unroll
        for (int ks = 0; ks < 4; ks++) {
            const uint32_t kb = (uint32_t)(ks * 32);

            uint32_t bh[4][2], bl[4][2];
            #pragma unroll
            for (int nt2 = 0; nt2 < 2; nt2++) {
                uint32_t t4[4];
                const uint32_t badd = boff + nt2 * 2048 + ((kb + bkb) ^ lxor);
                ldsm4(Bs_hi + badd, t4);
                bh[2 * nt2][0] = t4[0]; bh[2 * nt2][1] = t4[1];
                bh[2 * nt2 + 1][0] = t4[2]; bh[2 * nt2 + 1][1] = t4[3];
                ldsm4(Bs_lo + badd, t4);
                bl[2 * nt2][0] = t4[0]; bl[2 * nt2][1] = t4[1];
                bl[2 * nt2 + 1][0] = t4[2]; bl[2 * nt2 + 1][1] = t4[3];
            }

            #pragma unroll
            for (int mt = 0; mt < 2; mt++) {
                const uint32_t aadd = aoff + mt * 2048 + ((kb + akb) ^ lxor);
                uint32_t a4[4];
                ldsm4(As_hi + aadd, a4);
                #pragma unroll
                for (int nt = 0; nt < 4; nt++) {
                    mma16816(c[mt][nt], a4, bh[nt][0], bh[nt][1]);
                    mma16816(c[mt][nt], a4, bl[nt][0], bl[nt][1]);
                }
                ldsm4(As_lo + aadd, a4);
                #pragma unroll
                for (int nt = 0; nt < 4; nt++)
                    mma16816(c[mt][nt], a4, bh[nt][0], bh[nt][1]);
            }
        }
        __syncthreads();
    }

    float* Crow = Cg + ((size_t)b * M + my * 128) * N + nx * 128;
    const int qr = l >> 2, qc = l & 3;
    #pragma unroll
    for (int mt = 0; mt < 2; mt++) {
        const int m0 = warp_m * 32 + mt * 16;
        #pragma unroll
        for (int nt = 0; nt < 4; nt++) {
            const int n0 = warp_n * 32 + nt * 8 + 2 * qc;
            *reinterpret_cast<float2*>(&Crow[(size_t)(m0 + qr) * N + n0]) =
                make_float2(c[mt][nt][0], c[mt][nt][1]);
            *reinterpret_cast<float2*>(&Crow[(size_t)(m0 + qr + 8) * N + n0]) =
                make_float2(c[mt][nt][2], c[mt][nt][3]);
        }
    }
}

__global__ void __launch_bounds__(GTHREADS, 1)
gemm_g_k() { gemm_core<Tt, Tt, true>(Xhi_g, Xlo_g, Xhi_g, Xlo_g, G_buf); }

__global__ void __launch_bounds__(GTHREADS, 1)
gemm_d_k() { gemm_core<Tt, Oo, false>(Xhi_g, Xlo_g, Whi_g, Wlo_g, D_buf); }

// ============================================================
// Scan: R10/R14 structure, diagonal rewritten as FORWARD substitution.
// After computing u_tl, scatter u_tl*Gs[tl][tl2] into H[tl2>tl]:
// independent FMAs on a register array instead of a dependent
// LDS-fed backward chain. Same FLOPs, ~6x shorter critical path.
// ============================================================
__global__ void __launch_bounds__(128, 4)
scan_kernel(const int* __restrict__ obs, float* __restrict__ out)
{
    __shared__ __align__(16) float Gs[Tt * CH];   // 32 KB
    __shared__ float y_s[CH * 128];               // 16 KB

    const int tid  = threadIdx.x;
    const int rg   = blockIdx.x;
    const int b    = blockIdx.y;
    const int orow = rg * 128 + tid;

    const int  slot_o    = obs[tid];
    const bool have_slot = ((slot_o >> 7) == rg);
    const int  slot_lrow = slot_o & 127;

    const float4* Gb4 = reinterpret_cast<const float4*>(G_buf + (size_t)b * Tt * Tt);
    const float* Db   = D_buf + (size_t)b * Tt * Oo + orow;
    float*       Ub   = U_buf + (size_t)b * Tt * Oo + orow;
    float*       outb = out   + (size_t)b * Tt * NOBS;

    float P = 1.0f;

    for (int c = 0; c < NCH; c++) {
        const int t0   = c * CH;
        const int rows = t0 + CH;

        // prefetch this chunk's D values (independent LDGs, MLP=32)
        float dv[CH];
        #pragma unroll
        for (int tl = 0; tl < CH; tl++) dv[tl] = Db[(t0 + tl) * Oo];

        __syncthreads();
        // stage Gs[j][tl] = G[b][j][t0+tl], j < rows, as float4
        {
            float4* dst = reinterpret_cast<float4*>(Gs);
            for (int i = tid; i < rows * 8; i += 128) {
                const int j = i >> 3, q = i & 7;
                dst[i] = Gb4[j * (Tt / 4) + t0 / 4 + q];
            }
        }
        __syncthreads();

        // ---- history: H[tl] = sum_{j<t0} u_j * Gs[j][tl], MLP-8 u loads ----
        u64 hacc[CH / 2];
        #pragma unroll
        for (int q = 0; q < CH / 2; q++) hacc[q] = 0;

        for (int j = 0; j < t0; j += 8) {
            float up[8];
            #pragma unroll
            for (int q = 0; q < 8; q++) up[q] = Ub[(j + q) * Oo];
            #pragma unroll
            for (int q = 0; q < 8; q++) {
                const u64 u2 = pack2(up[q], up[q]);
                const ulonglong2* grow = (const ulonglong2*)&Gs[(j + q) * CH];
                #pragma unroll
                for (int p = 0; p < CH / 4; p++) {
                    ulonglong2 gg = grow[p];
                    hacc[2 * p]     = ffma2(u2, gg.x, hacc[2 * p]);
                    hacc[2 * p + 1] = ffma2(u2, gg.y, hacc[2 * p + 1]);
                }
            }
        }
        float H[CH];
        #pragma unroll
        for (int q = 0; q < CH / 2; q++) unpack2(hacc[q], H[2 * q], H[2 * q + 1]);

        // ---- serial diagonal, forward-substitution form ----
        #pragma unroll
        for (int tl = 0; tl < CH; tl++) {
            const float pre = P * (dv[tl] + H[tl]);
            const float y   = 1.0f / (1.0f + __expf(-pre));
            const float c1  = 1.0f - ETA * y * y;
            P *= c1;
            const float u = __fdividef(ETA * y, P);
            Ub[(t0 + tl) * Oo]  = u;
            y_s[tl * 128 + tid] = y;
            // scatter forward: independent FMAs, freely schedulable
            const float* grow = &Gs[(t0 + tl) * CH];
            #pragma unroll
            for (int tl2 = tl + 1; tl2 < CH; tl2++)
                H[tl2] = fmaf(u, grow[tl2], H[tl2]);
        }
        __syncthreads();

        if (have_slot) {
            #pragma unroll 4
            for (int tl = 0; tl < CH; tl++)
                outb[(t0 + tl) * NOBS + tid] = y_s[tl * 128 + slot_lrow];
        }
    }
}

extern "C" void kernel_launch(void* const* d_in, const int* in_sizes, int n_in,
                              void* d_out, int out_size)
{
    const float* X  = (const float*)d_in[0];
    const float* Wi = (const float*)d_in[1];
    const int* obs  = (const int*)d_in[2];
    float* out      = (float*)d_out;

    cudaFuncSetAttribute(gemm_g_k, cudaFuncAttributeMaxDynamicSharedMemorySize, SM_TOTAL);
    cudaFuncSetAttribute(gemm_d_k, cudaFuncAttributeMaxDynamicSharedMemorySize, SM_TOTAL);

    const int nX4 = Bb * Tt * Ii / 4;
    const int nW4 = Bb * Oo * Ii / 4;
    split_x<<<(nX4 + 255) / 256, 256>>>(X);
    split_w<<<(nW4 + 255) / 256, 256>>>(Wi);

    gemm_g_k<<<dim3(Tt / 128, Tt / 128, Bb), GTHREADS, SM_TOTAL>>>();
    gemm_d_k<<<dim3(Oo / 128, Tt / 128, Bb), GTHREADS, SM_TOTAL>>>();

    scan_kernel<<<dim3(Oo / 128, Bb), 128>>>(obs, out);
}

// round 16
// speedup vs baseline: 1.6677x; 1.0950x over previous
#include <cuda_runtime.h>
#include <cuda_bf16.h>
#include <cstdint>

#define Bb   64
#define Tt   256
#define Ii   512
#define Oo   512
#define NOBS 128
#define ETA  0.01f
#define CH   32
#define NCH  (Tt / CH)

typedef unsigned long long u64;

// ---- scratch (static __device__, no allocs) ----
__device__ __align__(16) float G_buf[Bb * Tt * Tt];
__device__ __align__(16) float D_buf[Bb * Tt * Oo];
__device__ __align__(16) float U_buf[Bb * Tt * Oo];
__device__ __align__(16) __nv_bfloat16 Xhi_g[Bb * Tt * Ii];
__device__ __align__(16) __nv_bfloat16 Xlo_g[Bb * Tt * Ii];
__device__ __align__(16) __nv_bfloat16 Whi_g[Bb * Oo * Ii];
__device__ __align__(16) __nv_bfloat16 Wlo_g[Bb * Oo * Ii];

// ---- packed f32x2 helpers ----
__device__ __forceinline__ u64 pack2(float x, float y) {
    u64 r; asm("mov.b64 %0, {%1, %2};" : "=l"(r) : "f"(x), "f"(y)); return r;
}
__device__ __forceinline__ void unpack2(u64 v, float& x, float& y) {
    asm("mov.b64 {%0, %1}, %2;" : "=f"(x), "=f"(y) : "l"(v));
}
__device__ __forceinline__ u64 ffma2(u64 a, u64 b, u64 c) {
    u64 d; asm("fma.rn.f32x2 %0, %1, %2, %3;" : "=l"(d) : "l"(a), "l"(b), "l"(c)); return d;
}

// ---- mma.sync / cp.async helpers ----
__device__ __forceinline__ uint32_t smem_u32(const void* p) {
    uint32_t a;
    asm("{ .reg .u64 t; cvta.to.shared.u64 t, %1; cvt.u32.u64 %0, t; }" : "=r"(a) : "l"(p));
    return a;
}
__device__ __forceinline__ void ldsm4(uint32_t addr, uint32_t r[4]) {
    asm volatile("ldmatrix.sync.aligned.m8n8.x4.shared.b16 {%0,%1,%2,%3}, [%4];"
                 : "=r"(r[0]), "=r"(r[1]), "=r"(r[2]), "=r"(r[3]) : "r"(addr));
}
__device__ __forceinline__ void mma16816(float c[4], const uint32_t a[4],
                                         uint32_t b0, uint32_t b1) {
    asm volatile("mma.sync.aligned.m16n8k16.row.col.f32.bf16.bf16.f32 "
                 "{%0,%1,%2,%3}, {%4,%5,%6,%7}, {%8,%9}, {%0,%1,%2,%3};"
                 : "+f"(c[0]), "+f"(c[1]), "+f"(c[2]), "+f"(c[3])
                 : "r"(a[0]), "r"(a[1]), "r"(a[2]), "r"(a[3]), "r"(b0), "r"(b1));
}
#define CP_ASYNC16(dst, src) asm volatile("cp.async.cg.shared.global [%0], [%1], 16;" :: "r"(dst), "l"(src))
#define CP_COMMIT()          asm volatile("cp.async.commit_group;" ::: "memory")
#define CP_WAIT(n)           asm volatile("cp.async.wait_group %0;" :: "n"(n) : "memory")

#define SWZ(x) ((x) ^ (((x) >> 3) & 0x70))

// ============================================================
// bf16 hi/lo split conversion (fused X+W, one launch)
// ============================================================
__device__ __forceinline__ void split_store(const float* __restrict__ src,
                                            __nv_bfloat16* __restrict__ hi,
                                            __nv_bfloat16* __restrict__ lo, int i)
{
    float4 v = reinterpret_cast<const float4*>(src)[i];
    __nv_bfloat16 h0 = __float2bfloat16(v.x), h1 = __float2bfloat16(v.y);
    __nv_bfloat16 h2 = __float2bfloat16(v.z), h3 = __float2bfloat16(v.w);
    __nv_bfloat16 l0 = __float2bfloat16(v.x - __bfloat162float(h0));
    __nv_bfloat16 l1 = __float2bfloat16(v.y - __bfloat162float(h1));
    __nv_bfloat16 l2 = __float2bfloat16(v.z - __bfloat162float(h2));
    __nv_bfloat16 l3 = __float2bfloat16(v.w - __bfloat162float(h3));
    reinterpret_cast<__nv_bfloat162*>(hi)[2 * i]     = __nv_bfloat162(h0, h1);
    reinterpret_cast<__nv_bfloat162*>(hi)[2 * i + 1] = __nv_bfloat162(h2, h3);
    reinterpret_cast<__nv_bfloat162*>(lo)[2 * i]     = __nv_bfloat162(l0, l1);
    reinterpret_cast<__nv_bfloat162*>(lo)[2 * i + 1] = __nv_bfloat162(l2, l3);
}

#define NX4 (Bb * Tt * Ii / 4)
#define NW4 (Bb * Oo * Ii / 4)
#define SPLIT_BLOCKS ((NX4 + NW4 + 255) / 256)

__global__ void __launch_bounds__(256)
split_all(const float* __restrict__ X, const float* __restrict__ W)
{
    int i = blockIdx.x * 256 + threadIdx.x;
    if (i < NX4) {
        split_store(X, Xhi_g, Xlo_g, i);
    } else {
        i -= NX4;
        if (i < NW4) split_store(W, Whi_g, Wlo_g, i);
    }
}

// ============================================================
// mma.sync bf16 3-term-split GEMM core (mainloop identical to R14/15;
// tile coords passed in so D and G can share one launch).
// 512 threads = 16 warps (4m x 4n), warp tile 32x32, 2-stage cp.async.
// ============================================================
#define KC       64
#define NKC      (Ii / KC)
#define SM_TILE  16384
#define SM_STAGE (4 * SM_TILE)   // 64 KB
#define SM_TOTAL (2 * SM_STAGE)  // 128 KB
#define GTHREADS 512

template<int M, int N>
__device__ __forceinline__ void gemm_core(int nx, int my, int b,
                                          const __nv_bfloat16* __restrict__ AH,
                                          const __nv_bfloat16* __restrict__ AL,
                                          const __nv_bfloat16* __restrict__ BH,
                                          const __nv_bfloat16* __restrict__ BL,
                                          float* __restrict__ Cg)
{
    extern __shared__ __align__(1024) char smem[];
    const uint32_t sb = smem_u32(smem);
    const int tid = threadIdx.x;
    const int wid = tid >> 5;
    const int l   = tid & 31;

    const int warp_m = wid & 3;
    const int warp_n = wid >> 2;

    const __nv_bfloat16* gbase[4];
    gbase[0] = AH + ((size_t)b * M + my * 128) * Ii;
    gbase[1] = AL + ((size_t)b * M + my * 128) * Ii;
    gbase[2] = BH + ((size_t)b * N + nx * 128) * Ii;
    gbase[3] = BL + ((size_t)b * N + nx * 128) * Ii;

    int  s_arr[8], s_rw[8], s_un[8];
    uint32_t s_dst[8];
    #pragma unroll
    for (int i = 0; i < 8; i++) {
        const int u = tid + GTHREADS * i;
        s_arr[i] = u >> 10;
        const int rem = u & 1023;
        s_rw[i] = rem >> 3;
        s_un[i] = rem & 7;
        s_dst[i] = (uint32_t)(s_arr[i] * SM_TILE + SWZ(s_rw[i] * 128 + s_un[i] * 16));
    }

    const int g = l >> 3, r = l & 7;
    const uint32_t aoff = (uint32_t)(warp_m * 32 + (g & 1) * 8 + r) * 128;
    const uint32_t akb  = (uint32_t)((g >> 1) * 16);
    const uint32_t boff = (uint32_t)(warp_n * 32 + (g >> 1) * 8 + r) * 128;
    const uint32_t bkb  = (uint32_t)((g & 1) * 16);
    const uint32_t lxor = (uint32_t)(r << 4);

    float c[2][4][4];
    #pragma unroll
    for (int mt = 0; mt < 2; mt++)
        #pragma unroll
        for (int nt = 0; nt < 4; nt++)
            #pragma unroll
            for (int q = 0; q < 4; q++) c[mt][nt][q] = 0.0f;

    #pragma unroll
    for (int i = 0; i < 8; i++) {
        const __nv_bfloat16* src = gbase[s_arr[i]] + (size_t)s_rw[i] * Ii + s_un[i] * 8;
        CP_ASYNC16(sb + s_dst[i], src);
    }
    CP_COMMIT();

    for (int ck = 0; ck < NKC; ck++) {
        const uint32_t buf = sb + (uint32_t)((ck & 1) * SM_STAGE);

        if (ck + 1 < NKC) {
            const uint32_t nbuf = (uint32_t)(((ck + 1) & 1) * SM_STAGE);
            const int koff = (ck + 1) * KC;
            #pragma unroll
            for (int i = 0; i < 8; i++) {
                const __nv_bfloat16* src =
                    gbase[s_arr[i]] + (size_t)s_rw[i] * Ii + koff + s_un[i] * 8;
                CP_ASYNC16(sb + nbuf + s_dst[i], src);
            }
            CP_COMMIT();
            CP_WAIT(1);
        } else {
            CP_WAIT(0);
        }
        __syncthreads();

        const uint32_t As_hi = buf;
        const uint32_t As_lo = buf + SM_TILE;
        const uint32_t Bs_hi = buf + 2 * SM_TILE;
        const uint32_t Bs_lo = buf + 3 * SM_TILE;

        #pragma unroll
        for (int ks = 0; ks < 4; ks++) {
            const uint32_t kb = (uint32_t)(ks * 32);

            uint32_t bh[4][2], bl[4][2];
            #pragma unroll
            for (int nt2 = 0; nt2 < 2; nt2++) {
                uint32_t t4[4];
                const uint32_t badd = boff + nt2 * 2048 + ((kb + bkb) ^ lxor);
                ldsm4(Bs_hi + badd, t4);
                bh[2 * nt2][0] = t4[0]; bh[2 * nt2][1] = t4[1];
                bh[2 * nt2 + 1][0] = t4[2]; bh[2 * nt2 + 1][1] = t4[3];
                ldsm4(Bs_lo + badd, t4);
                bl[2 * nt2][0] = t4[0]; bl[2 * nt2][1] = t4[1];
                bl[2 * nt2 + 1][0] = t4[2]; bl[2 * nt2 + 1][1] = t4[3];
            }

            #pragma unroll
            for (int mt = 0; mt < 2; mt++) {
                const uint32_t aadd = aoff + mt * 2048 + ((kb + akb) ^ lxor);
                uint32_t a4[4];
                ldsm4(As_hi + aadd, a4);
                #pragma unroll
                for (int nt = 0; nt < 4; nt++) {
                    mma16816(c[mt][nt], a4, bh[nt][0], bh[nt][1]);
                    mma16816(c[mt][nt], a4, bl[nt][0], bl[nt][1]);
                }
                ldsm4(As_lo + aadd, a4);
                #pragma unroll
                for (int nt = 0; nt < 4; nt++)
                    mma16816(c[mt][nt], a4, bh[nt][0], bh[nt][1]);
            }
        }
        __syncthreads();
    }

    float* Crow = Cg + ((size_t)b * M + my * 128) * N + nx * 128;
    const int qr = l >> 2, qc = l & 3;
    #pragma unroll
    for (int mt = 0; mt < 2; mt++) {
        const int m0 = warp_m * 32 + mt * 16;
        #pragma unroll
        for (int nt = 0; nt < 4; nt++) {
            const int n0 = warp_n * 32 + nt * 8 + 2 * qc;
            *reinterpret_cast<float2*>(&Crow[(size_t)(m0 + qr) * N + n0]) =
                make_float2(c[mt][nt][0], c[mt][nt][1]);
            *reinterpret_cast<float2*>(&Crow[(size_t)(m0 + qr + 8) * N + n0]) =
                make_float2(c[mt][nt][2], c[mt][nt][3]);
        }
    }
}

// Fused launch: grid (6, 2, 64). x<4 -> D tile (x, y); x>=4 -> G tile (x-4, y).
__global__ void __launch_bounds__(GTHREADS, 1)
gemm_all_k()
{
    const int x = blockIdx.x, y = blockIdx.y, b = blockIdx.z;
    if (x < 4) {
        gemm_core<Tt, Oo>(x, y, b, Xhi_g, Xlo_g, Whi_g, Wlo_g, D_buf);
    } else {
        const int gx = x - 4;
        if (y > gx) return;                 // TRI skip (only j<=t tiles needed)
        gemm_core<Tt, Tt>(gx, y, b, Xhi_g, Xlo_g, Xhi_g, Xlo_g, G_buf);
    }
}

// ============================================================
// Scan (R15 structure: proven 275 us run; forward substitution)
// ============================================================
__global__ void __launch_bounds__(128, 4)
scan_kernel(const int* __restrict__ obs, float* __restrict__ out)
{
    __shared__ __align__(16) float Gs[Tt * CH];   // 32 KB
    __shared__ float y_s[CH * 128];               // 16 KB

    const int tid  = threadIdx.x;
    const int rg   = blockIdx.x;
    const int b    = blockIdx.y;
    const int orow = rg * 128 + tid;

    const int  slot_o    = obs[tid];
    const bool have_slot = ((slot_o >> 7) == rg);
    const int  slot_lrow = slot_o & 127;

    const float4* Gb4 = reinterpret_cast<const float4*>(G_buf + (size_t)b * Tt * Tt);
    const float* Db   = D_buf + (size_t)b * Tt * Oo + orow;
    float*       Ub   = U_buf + (size_t)b * Tt * Oo + orow;
    float*       outb = out   + (size_t)b * Tt * NOBS;

    float P = 1.0f;

    for (int c = 0; c < NCH; c++) {
        const int t0   = c * CH;
        const int rows = t0 + CH;

        float dv[CH];
        #pragma unroll
        for (int tl = 0; tl < CH; tl++) dv[tl] = Db[(t0 + tl) * Oo];

        __syncthreads();
        {
            float4* dst = reinterpret_cast<float4*>(Gs);
            for (int i = tid; i < rows * 8; i += 128) {
                const int j = i >> 3, q = i & 7;
                dst[i] = Gb4[j * (Tt / 4) + t0 / 4 + q];
            }
        }
        __syncthreads();

        u64 hacc[CH / 2];
        #pragma unroll
        for (int q = 0; q < CH / 2; q++) hacc[q] = 0;

        for (int j = 0; j < t0; j += 8) {
            float up[8];
            #pragma unroll
            for (int q = 0; q < 8; q++) up[q] = Ub[(j + q) * Oo];
            #pragma unroll
            for (int q = 0; q < 8; q++) {
                const u64 u2 = pack2(up[q], up[q]);
                const ulonglong2* grow = (const ulonglong2*)&Gs[(j + q) * CH];
                #pragma unroll
                for (int p = 0; p < CH / 4; p++) {
                    ulonglong2 gg = grow[p];
                    hacc[2 * p]     = ffma2(u2, gg.x, hacc[2 * p]);
                    hacc[2 * p + 1] = ffma2(u2, gg.y, hacc[2 * p + 1]);
                }
            }
        }
        float H[CH];
        #pragma unroll
        for (int q = 0; q < CH / 2; q++) unpack2(hacc[q], H[2 * q], H[2 * q + 1]);

        #pragma unroll
        for (int tl = 0; tl < CH; tl++) {
            const float pre = P * (dv[tl] + H[tl]);
            const float y   = 1.0f / (1.0f + __expf(-pre));
            const float c1  = 1.0f - ETA * y * y;
            P *= c1;
            const float u = __fdividef(ETA * y, P);
            Ub[(t0 + tl) * Oo]  = u;
            y_s[tl * 128 + tid] = y;
            const float* grow = &Gs[(t0 + tl) * CH];
            #pragma unroll
            for (int tl2 = tl + 1; tl2 < CH; tl2++)
                H[tl2] = fmaf(u, grow[tl2], H[tl2]);
        }
        __syncthreads();

        if (have_slot) {
            #pragma unroll 4
            for (int tl = 0; tl < CH; tl++)
                outb[(t0 + tl) * NOBS + tid] = y_s[tl * 128 + slot_lrow];
        }
    }
}

extern "C" void kernel_launch(void* const* d_in, const int* in_sizes, int n_in,
                              void* d_out, int out_size)
{
    const float* X  = (const float*)d_in[0];
    const float* Wi = (const float*)d_in[1];
    const int* obs  = (const int*)d_in[2];
    float* out      = (float*)d_out;

    cudaFuncSetAttribute(gemm_all_k, cudaFuncAttributeMaxDynamicSharedMemorySize, SM_TOTAL);

    split_all<<<SPLIT_BLOCKS, 256>>>(X, Wi);
    gemm_all_k<<<dim3(6, 2, Bb), GTHREADS, SM_TOTAL>>>();
    scan_kernel<<<dim3(Oo / 128, Bb), 128>>>(obs, out);
}